// round 1
// baseline (speedup 1.0000x reference)
#include <cuda_runtime.h>
#include <cuda_bf16.h>

// ---------------------------------------------------------------------------
// HybridQLSTM: RX-encode + RX(theta) + CNOT ring + <Z> has the closed form
//   qlayer(y, th)_w = product of cos(y_v + th_v) over a wire subset:
//     out0 = c1*c2*c3, out1 = c0*c1, out2 = c0*c1*c2, out3 = c0*c1*c2*c3
// LSTM input projection splits into a parallel embedding part (E=1024) and a
// tiny sequential h part (H=4). Three kernels:
//   k_pre  : [T,16] = emb[sent]·W[:, :E].T + b + theta   (parallel, HBM-bound)
//   k_scan : 8192-step recurrence on ONE warp (16 active lanes)
//   k_tag  : 50-wide tag logits + log_softmax            (parallel)
// ---------------------------------------------------------------------------

#define T_MAX 8192

__device__ float g_pre[(T_MAX + 4) * 16];   // padded for prefetch overrun
__device__ float g_h[T_MAX * 4];

__device__ __forceinline__ void fma4(float4& a, float4 x, float4 w) {
    a.x = fmaf(x.x, w.x, a.x);
    a.y = fmaf(x.y, w.y, a.y);
    a.z = fmaf(x.z, w.z, a.z);
    a.w = fmaf(x.w, w.w, a.w);
}

// ---------------------------------------------------------------------------
// Kernel 1: one block per token, 4 warps; warp g computes gate g's 4 rows.
// pre[t][4g+j] = b_g[j] + th_g[j] + sum_e emb[sent[t]][e] * W_g[j][e]
// W_g rows are length D=1028; only the first 1024 columns are used here
// (columns 1024..1027 are the h-recurrence weights, consumed by k_scan).
// ---------------------------------------------------------------------------
__global__ void k_pre(const int* __restrict__ sent, const float* __restrict__ emb,
                      const float* __restrict__ Wf, const float* __restrict__ bf,
                      const float* __restrict__ Wi, const float* __restrict__ bi,
                      const float* __restrict__ Wu, const float* __restrict__ bu,
                      const float* __restrict__ Wo, const float* __restrict__ bo,
                      const float* __restrict__ thf, const float* __restrict__ thi,
                      const float* __restrict__ thu, const float* __restrict__ tho)
{
    int t = blockIdx.x;
    int warp = threadIdx.x >> 5;
    int lane = threadIdx.x & 31;

    const float* Wg = (warp == 0) ? Wf : (warp == 1) ? Wi : (warp == 2) ? Wu : Wo;
    const float* bg = (warp == 0) ? bf : (warp == 1) ? bi : (warp == 2) ? bu : bo;
    const float* tg = (warp == 0) ? thf : (warp == 1) ? thi : (warp == 2) ? thu : tho;

    const float4* e4 = (const float4*)(emb + (size_t)sent[t] * 1024);
    const float4* W4 = (const float4*)Wg;   // row stride = 1028 floats = 257 float4

    float4 a0 = make_float4(0.f, 0.f, 0.f, 0.f);
    float4 a1 = a0, a2 = a0, a3 = a0;

    #pragma unroll
    for (int k = lane; k < 256; k += 32) {
        float4 x = e4[k];
        fma4(a0, x, W4[k]);
        fma4(a1, x, W4[257 + k]);
        fma4(a2, x, W4[514 + k]);
        fma4(a3, x, W4[771 + k]);
    }

    float s0 = (a0.x + a0.y) + (a0.z + a0.w);
    float s1 = (a1.x + a1.y) + (a1.z + a1.w);
    float s2 = (a2.x + a2.y) + (a2.z + a2.w);
    float s3 = (a3.x + a3.y) + (a3.z + a3.w);

    #pragma unroll
    for (int off = 16; off; off >>= 1) {
        s0 += __shfl_xor_sync(0xFFFFFFFFu, s0, off);
        s1 += __shfl_xor_sync(0xFFFFFFFFu, s1, off);
        s2 += __shfl_xor_sync(0xFFFFFFFFu, s2, off);
        s3 += __shfl_xor_sync(0xFFFFFFFFu, s3, off);
    }

    if (lane == 0) {
        float* dst = g_pre + t * 16 + warp * 4;
        dst[0] = s0 + bg[0] + tg[0];
        dst[1] = s1 + bg[1] + tg[1];
        dst[2] = s2 + bg[2] + tg[2];
        dst[3] = s3 + bg[3] + tg[3];
    }
}

// ---------------------------------------------------------------------------
// Kernel 2: sequential scan on one warp. Lane layout: eff = lane&15 = 4g+w
// (gate g: 0=f,1=i,2=u,3=o; wire/hidden-unit w). Upper 16 lanes mirror the
// lower 16 so full-mask shuffles stay trivially converged.
// Every lane maintains c_w and h_w for its OWN w (replicated across gates).
// ---------------------------------------------------------------------------
__device__ __forceinline__ void scan_step(
    float pv, float4 wh, int g, int w, int base,
    float& c_state, float& h_own)
{
    const unsigned F = 0xFFFFFFFFu;

    // gather h (each quad-mate (g,k) holds h_k)
    float h0 = __shfl_sync(F, h_own, base + 0);
    float h1 = __shfl_sync(F, h_own, base + 1);
    float h2 = __shfl_sync(F, h_own, base + 2);
    float h3 = __shfl_sync(F, h_own, base + 3);

    float z = fmaf(wh.x, h0, pv);
    z = fmaf(wh.y, h1, z);
    z = fmaf(wh.z, h2, z);
    z = fmaf(wh.w, h3, z);          // pre already includes b + theta

    float cz  = __cosf(z);
    float nbr = __shfl_xor_sync(F, cz, 1);     // cos of wire w^1, same gate
    float pw  = cz * nbr;                      // pair product (c0c1 or c2c3)
    float po  = __shfl_xor_sync(F, pw, 2);     // the other pair's product

    // out0=c1c2c3  out1=c0c1  out2=c0c1c2  out3=c0c1c2c3
    float m1  = (w & 1) ? pw : ((w == 0) ? nbr : cz);
    float out = (w == 1) ? pw : (m1 * po);

    // gate f,i,o: sigmoid(x)=1/(1+e^-x); gate u: tanh(x)=2/(1+e^-2x)-1
    bool  isU = (g == 2);
    float e   = __expf(isU ? (-2.f * out) : (-out));
    float r   = __fdividef(1.f, 1.f + e);
    float act = isU ? fmaf(2.f, r, -1.f) : r;

    // transpose: lane (g,w) pulls gate values for hidden unit w
    float fv = __shfl_sync(F, act, w + 0);
    float iv = __shfl_sync(F, act, w + 4);
    float uv = __shfl_sync(F, act, w + 8);
    float ov = __shfl_sync(F, act, w + 12);

    c_state = fmaf(fv, c_state, iv * uv);

    float ec = __expf(-2.f * c_state);
    float tc = fmaf(2.f, __fdividef(1.f, 1.f + ec), -1.f);
    h_own = ov * tc;
}

__global__ void k_scan(const float* __restrict__ Wf, const float* __restrict__ Wi,
                       const float* __restrict__ Wu, const float* __restrict__ Wo,
                       int T)
{
    int lane = threadIdx.x & 31;
    int eff  = lane & 15;
    int g    = eff >> 2;
    int w    = eff & 3;
    int base = eff & ~3;

    const float* Wg = (g == 0) ? Wf : (g == 1) ? Wi : (g == 2) ? Wu : Wo;
    // recurrence weights: W_g[w][1024..1027], 16B-aligned
    float4 wh = *(const float4*)(Wg + w * 1028 + 1024);

    const float* pp = g_pre + eff;   // stride 16 floats per timestep
    float c_state = 0.f, h_own = 0.f;
    bool  st = (lane < 4);           // g=0 lanes write h_w

    float pv0 = pp[0];
    float pv1 = pp[16];

    #pragma unroll 1
    for (int t = 0; t < T; t += 2) {
        float nv0 = pp[(t + 2) * 16];          // prefetch distance 2 (padded)
        scan_step(pv0, wh, g, w, base, c_state, h_own);
        if (st) g_h[t * 4 + lane] = h_own;
        pv0 = nv0;

        float nv1 = pp[(t + 3) * 16];
        scan_step(pv1, wh, g, w, base, c_state, h_own);
        if (st) g_h[(t + 1) * 4 + lane] = h_own;
        pv1 = nv1;
    }
}

// ---------------------------------------------------------------------------
// Kernel 3: one warp per token; lane handles tags {lane, lane+32} (TAG=50).
// logits = h[4] @ Wt.T + bt, then log_softmax over 50.
// ---------------------------------------------------------------------------
__global__ void k_tag(const float* __restrict__ Wt, const float* __restrict__ bt,
                      float* __restrict__ out)
{
    const unsigned F = 0xFFFFFFFFu;
    int warp = threadIdx.x >> 5;
    int lane = threadIdx.x & 31;
    int t = blockIdx.x * 4 + warp;

    float4 h = *(const float4*)(g_h + t * 4);

    float4 w1 = *(const float4*)(Wt + lane * 4);
    float l1 = bt[lane] + h.x * w1.x + h.y * w1.y + h.z * w1.z + h.w * w1.w;

    int   k2 = lane + 32;
    float l2 = __int_as_float(0xff800000);     // -inf
    if (k2 < 50) {
        float4 w2 = *(const float4*)(Wt + k2 * 4);
        l2 = bt[k2] + h.x * w2.x + h.y * w2.y + h.z * w2.z + h.w * w2.w;
    }

    float m = fmaxf(l1, l2);
    #pragma unroll
    for (int off = 16; off; off >>= 1)
        m = fmaxf(m, __shfl_xor_sync(F, m, off));

    float s = expf(l1 - m) + ((k2 < 50) ? expf(l2 - m) : 0.f);
    #pragma unroll
    for (int off = 16; off; off >>= 1)
        s += __shfl_xor_sync(F, s, off);

    float lse = m + logf(s);
    out[t * 50 + lane] = l1 - lse;
    if (k2 < 50) out[t * 50 + k2] = l2 - lse;
}

// ---------------------------------------------------------------------------
extern "C" void kernel_launch(void* const* d_in, const int* in_sizes, int n_in,
                              void* d_out, int out_size)
{
    const int*   sent = (const int*)  d_in[0];
    const float* emb  = (const float*)d_in[1];
    const float* Wf   = (const float*)d_in[2];
    const float* bf   = (const float*)d_in[3];
    const float* Wi   = (const float*)d_in[4];
    const float* bi   = (const float*)d_in[5];
    const float* Wu   = (const float*)d_in[6];
    const float* bu   = (const float*)d_in[7];
    const float* Wo   = (const float*)d_in[8];
    const float* bo   = (const float*)d_in[9];
    const float* thf  = (const float*)d_in[10];
    const float* thi  = (const float*)d_in[11];
    const float* thu  = (const float*)d_in[12];
    const float* tho  = (const float*)d_in[13];
    const float* Wt   = (const float*)d_in[14];
    const float* bt   = (const float*)d_in[15];
    float* out = (float*)d_out;

    int T = in_sizes[0];
    if (T > T_MAX) T = T_MAX;

    k_pre <<<T, 128>>>(sent, emb, Wf, bf, Wi, bi, Wu, bu, Wo, bo, thf, thi, thu, tho);
    k_scan<<<1, 32>>>(Wf, Wi, Wu, Wo, T);
    k_tag <<<T / 4, 128>>>(Wt, bt, out);
}

// round 2
// speedup vs baseline: 1.3893x; 1.3893x over previous
#include <cuda_runtime.h>
#include <cuda_bf16.h>

// ---------------------------------------------------------------------------
// HybridQLSTM closed form:
//   qlayer(y)_w = product of cos(y_v) over: out0=c1c2c3, out1=c0c1,
//                 out2=c0c1c2, out3=c0c1c2c3
// k_pre  : [T,16] embedding-part projection (parallel, 4 tokens/block)
// k_scan : 8192-step recurrence, ONE warp, 3 parallel-shuffle stages/step,
//          MUFU.TANH activations
// k_tag  : 50-wide logits + log_softmax
// ---------------------------------------------------------------------------

#define T_MAX 8192

__device__ float g_pre[(T_MAX + 4) * 16];   // padded for prefetch overrun
__device__ float g_h[T_MAX * 4];

__device__ __forceinline__ void fma4(float4& a, float4 x, float4 w) {
    a.x = fmaf(x.x, w.x, a.x);
    a.y = fmaf(x.y, w.y, a.y);
    a.z = fmaf(x.z, w.z, a.z);
    a.w = fmaf(x.w, w.w, a.w);
}

__device__ __forceinline__ float tanhf_fast(float x) {
    float y;
    asm("tanh.approx.f32 %0, %1;" : "=f"(y) : "f"(x));
    return y;
}

// ---------------------------------------------------------------------------
// Kernel 1: 4 tokens per block, 4 warps; warp g computes gate g's 4 rows for
// all 4 tokens. W rows (stride 1028 floats) are loaded once per k-iter and
// reused across the 4 tokens -> L1 traffic per token drops ~3.4x.
// ---------------------------------------------------------------------------
__global__ void k_pre(const int* __restrict__ sent, const float* __restrict__ emb,
                      const float* __restrict__ Wf, const float* __restrict__ bf,
                      const float* __restrict__ Wi, const float* __restrict__ bi,
                      const float* __restrict__ Wu, const float* __restrict__ bu,
                      const float* __restrict__ Wo, const float* __restrict__ bo,
                      const float* __restrict__ thf, const float* __restrict__ thi,
                      const float* __restrict__ thu, const float* __restrict__ tho,
                      int T)
{
    int t0   = blockIdx.x * 4;
    int warp = threadIdx.x >> 5;
    int lane = threadIdx.x & 31;

    const float* Wg = (warp == 0) ? Wf : (warp == 1) ? Wi : (warp == 2) ? Wu : Wo;
    const float* bg = (warp == 0) ? bf : (warp == 1) ? bi : (warp == 2) ? bu : bo;
    const float* tg = (warp == 0) ? thf : (warp == 1) ? thi : (warp == 2) ? thu : tho;

    const float4* W4 = (const float4*)Wg;   // row stride = 257 float4

    const float4* e[4];
    #pragma unroll
    for (int j = 0; j < 4; j++) {
        int t = t0 + j;
        int s = (t < T) ? sent[t] : sent[0];
        e[j] = (const float4*)(emb + (size_t)s * 1024);
    }

    float4 acc[4][4];                       // [row][token]
    #pragma unroll
    for (int r = 0; r < 4; r++)
        #pragma unroll
        for (int j = 0; j < 4; j++)
            acc[r][j] = make_float4(0.f, 0.f, 0.f, 0.f);

    for (int k = lane; k < 256; k += 32) {
        float4 w0 = W4[k];
        float4 w1 = W4[257 + k];
        float4 w2 = W4[514 + k];
        float4 w3 = W4[771 + k];
        #pragma unroll
        for (int j = 0; j < 4; j++) {
            float4 x = e[j][k];
            fma4(acc[0][j], x, w0);
            fma4(acc[1][j], x, w1);
            fma4(acc[2][j], x, w2);
            fma4(acc[3][j], x, w3);
        }
    }

    #pragma unroll
    for (int r = 0; r < 4; r++) {
        #pragma unroll
        for (int j = 0; j < 4; j++) {
            float4 a = acc[r][j];
            float s = (a.x + a.y) + (a.z + a.w);
            #pragma unroll
            for (int off = 16; off; off >>= 1)
                s += __shfl_xor_sync(0xFFFFFFFFu, s, off);
            if (lane == 0 && (t0 + j) < T)
                g_pre[(t0 + j) * 16 + warp * 4 + r] = s + bg[r] + tg[r];
        }
    }
}

// ---------------------------------------------------------------------------
// Kernel 2: sequential scan, one warp. Lane layout eff = lane&15 = 4g+w
// (gate g: 0=f,1=i,2=u,3=o; wire w). Upper 16 lanes mirror lower 16.
// Per step, 3 parallel-shuffle stages:
//   1) gather h0..h3   2) xor 1/2/3 for all-cosine exchange   3) gate transpose
// ---------------------------------------------------------------------------
__global__ void k_scan(const float* __restrict__ Wf, const float* __restrict__ Wi,
                       const float* __restrict__ Wu, const float* __restrict__ Wo,
                       int T)
{
    const unsigned F = 0xFFFFFFFFu;
    int lane = threadIdx.x & 31;
    int eff  = lane & 15;
    int g    = eff >> 2;
    int w    = eff & 3;
    int base = eff & ~3;

    const float* Wg = (g == 0) ? Wf : (g == 1) ? Wi : (g == 2) ? Wu : Wo;
    float4 wh = *(const float4*)(Wg + w * 1028 + 1024);   // recurrence weights

    // per-lane constant selectors
    bool  isW0 = (w == 0), isW1 = (w == 1), isW2 = (w == 2);
    bool  isU  = (g == 2);
    float sArg = isU ? 1.0f : 0.5f;    // sigmoid(x)=0.5*tanh(x/2)+0.5
    float aA   = isU ? 1.0f : 0.5f;
    float aB   = isU ? 0.0f : 0.5f;

    const float* pp = g_pre + eff;     // stride 16 per timestep
    float c_state = 0.f, h_own = 0.f;
    bool  st = (lane < 4);             // lanes 0..3 write h_w

    float pv0 = pp[0];
    float pv1 = pp[16];

    #pragma unroll 1
    for (int t = 0; t < T; t += 2) {
        #pragma unroll
        for (int u = 0; u < 2; u++) {
            float pv = u ? pv1 : pv0;
            float nv = pp[(t + 2 + u) * 16];          // prefetch (padded)

            // stage 1: gather h
            float h0 = __shfl_sync(F, h_own, base + 0);
            float h1 = __shfl_sync(F, h_own, base + 1);
            float h2 = __shfl_sync(F, h_own, base + 2);
            float h3 = __shfl_sync(F, h_own, base + 3);

            // z (depth-12 tree); pre already includes b + theta
            float za = fmaf(wh.x, h0, pv);
            float zb = fmaf(wh.w, h3, wh.z * h2);
            float z  = fmaf(wh.y, h1, za) + zb;

            float v0 = __cosf(z);

            // stage 2: all-cosine exchange (3 parallel xors)
            float v1 = __shfl_xor_sync(F, v0, 1);
            float v2 = __shfl_xor_sync(F, v0, 2);
            float v3 = __shfl_xor_sync(F, v0, 3);

            // out0=v1*t23  out1=t01  out2=v0*t23  out3=t01*t23  (v_j = cos of wire w^j)
            float t01  = v0 * v1;
            float t23s = (v2 * v3) * sArg;
            float u01  = t01 * sArg;
            float m    = isW0 ? v1 : (isW2 ? v0 : t01);
            float arg  = isW1 ? u01 : m * t23s;

            float act = fmaf(aA, tanhf_fast(arg), aB);

            // stage 3: gate transpose (lane pulls f,i,u,o of its wire)
            float fv = __shfl_sync(F, act, w + 0);
            float iv = __shfl_sync(F, act, w + 4);
            float uv = __shfl_sync(F, act, w + 8);
            float ov = __shfl_sync(F, act, w + 12);

            c_state = fmaf(fv, c_state, iv * uv);
            h_own   = ov * tanhf_fast(c_state);

            if (st) g_h[(t + u) * 4 + lane] = h_own;
            if (u) pv1 = nv; else pv0 = nv;
        }
    }
}

// ---------------------------------------------------------------------------
// Kernel 3: one warp per token; lane handles tags {lane, lane+32} (TAG=50).
// ---------------------------------------------------------------------------
__global__ void k_tag(const float* __restrict__ Wt, const float* __restrict__ bt,
                      float* __restrict__ out)
{
    const unsigned F = 0xFFFFFFFFu;
    int warp = threadIdx.x >> 5;
    int lane = threadIdx.x & 31;
    int t = blockIdx.x * 4 + warp;

    float4 h = *(const float4*)(g_h + t * 4);

    float4 w1 = *(const float4*)(Wt + lane * 4);
    float l1 = bt[lane] + h.x * w1.x + h.y * w1.y + h.z * w1.z + h.w * w1.w;

    int   k2 = lane + 32;
    float l2 = __int_as_float(0xff800000);     // -inf
    if (k2 < 50) {
        float4 w2 = *(const float4*)(Wt + k2 * 4);
        l2 = bt[k2] + h.x * w2.x + h.y * w2.y + h.z * w2.z + h.w * w2.w;
    }

    float m = fmaxf(l1, l2);
    #pragma unroll
    for (int off = 16; off; off >>= 1)
        m = fmaxf(m, __shfl_xor_sync(F, m, off));

    float s = expf(l1 - m) + ((k2 < 50) ? expf(l2 - m) : 0.f);
    #pragma unroll
    for (int off = 16; off; off >>= 1)
        s += __shfl_xor_sync(F, s, off);

    float lse = m + logf(s);
    out[t * 50 + lane] = l1 - lse;
    if (k2 < 50) out[t * 50 + k2] = l2 - lse;
}

// ---------------------------------------------------------------------------
extern "C" void kernel_launch(void* const* d_in, const int* in_sizes, int n_in,
                              void* d_out, int out_size)
{
    const int*   sent = (const int*)  d_in[0];
    const float* emb  = (const float*)d_in[1];
    const float* Wf   = (const float*)d_in[2];
    const float* bf   = (const float*)d_in[3];
    const float* Wi   = (const float*)d_in[4];
    const float* bi   = (const float*)d_in[5];
    const float* Wu   = (const float*)d_in[6];
    const float* bu   = (const float*)d_in[7];
    const float* Wo   = (const float*)d_in[8];
    const float* bo   = (const float*)d_in[9];
    const float* thf  = (const float*)d_in[10];
    const float* thi  = (const float*)d_in[11];
    const float* thu  = (const float*)d_in[12];
    const float* tho  = (const float*)d_in[13];
    const float* Wt   = (const float*)d_in[14];
    const float* bt   = (const float*)d_in[15];
    float* out = (float*)d_out;

    int T = in_sizes[0];
    if (T > T_MAX) T = T_MAX;

    k_pre <<<(T + 3) / 4, 128>>>(sent, emb, Wf, bf, Wi, bi, Wu, bu, Wo, bo,
                                 thf, thi, thu, tho, T);
    k_scan<<<1, 32>>>(Wf, Wi, Wu, Wo, T);
    k_tag <<<T / 4, 128>>>(Wt, bt, out);
}